// round 12
// baseline (speedup 1.0000x reference)
#include <cuda_runtime.h>
#include <cstdint>
#include <cmath>

// HDCProcessor: bit-domain exponential-decay scan, single fused kernel.
// R12: CLEN 128 -> 256 (NCHUNK 8), WUP stays 128 -> warm overhead 2.0x -> 1.5x
//      (total warp-steps -25%); inv table only for chunks 0,1 (t>=512 ->
//      inv == 0.05f exactly in fp32).
//   hdc[t,d] = 0.3*s(t,d) + 0.7*s(t,d)*s(t-1,d-1)*s(t-2,d-2)  (signs, rolls mod D)
//   acc_t = 0.95*acc_{t-1} + hdc_t ;  out[t] = acc_t * (1-g)/(1-g^{t+1})
// c in {+-1.0, +-0.4}: smem LUT[f1 f0 y1 y0] = {c_j, c_j+1}, broadcast LDS.
// Chunk 0 exact; chunks >=1 use a 128-step warmup (truncation ~3.5e-4 rel,
// measured in R11; gate 1e-3).

#define DDIM     4096
#define NB       8
#define NT       2048
#define NCHUNK   8
#define CLEN     256
#define WUP      128
#define NTHREADS 128
#define NDG      8                 // 4096 dims / (128 thr * 4 dims)
#define ROWW     17                // words per staged row: 1 halo + 16 slice
#define RWORDS   (256 * ROWW)      // 4352
#define ROWB     (ROWW * 4)
#define SIDXN    (CLEN + WUP + 2)  // 386

__device__ uint32_t g_bitsx[NDG * RWORDS];   // per-dg pre-halo'd packed rows
__device__ float    g_inv[NT];               // (1-g)/(1-g^{t+1})

// ---- packed f32x2 helpers ----
__device__ __forceinline__ unsigned long long pk2(uint32_t lo, uint32_t hi) {
    unsigned long long r;
    asm("mov.b64 %0, {%1, %2};" : "=l"(r) : "r"(lo), "r"(hi));
    return r;
}
#define FMA2(d, a, b, c) \
    asm("fma.rn.f32x2 %0, %1, %2, %3;" : "=l"(d) : "l"(a), "l"(b), "l"(c))
#define MUL2(d, a, b) \
    asm("mul.rn.f32x2 %0, %1, %2;" : "=l"(d) : "l"(a), "l"(b))
#define G2    0x3F7333333F733333ull   // {0.95f, 0.95f}
#define INV05 0x3D4CCCCD3D4CCCCDull   // {0.05f, 0.05f}

// ---- pack: sign bits of the bipolar codebook, expanded per d-group ----
__global__ void pack_kernel(const float* __restrict__ cb) {
    const int row  = blockIdx.x;
    const int lane = threadIdx.x & 31;
    const int wq   = (blockIdx.y << 2) + (threadIdx.x >> 5);  // word quarter 0..15
    for (int k = 0; k < 8; k++) {
        int gw = wq * 8 + k;
        float v = cb[row * DDIM + gw * 32 + lane];
        unsigned m = __ballot_sync(0xffffffffu, v < 0.0f);
        if (lane == 0) {
            g_bitsx[(gw >> 4) * RWORDS + row * ROWW + (gw & 15) + 1] = m;
            int gwn = (gw + 1) & 127;               // this word is the halo of
            if ((gwn & 15) == 0)                    // the next d-group (mod wrap)
                g_bitsx[(gwn >> 4) * RWORDS + row * ROWW] = m;
        }
    }
    if (blockIdx.y == 0) {
        int gid = blockIdx.x * NTHREADS + threadIdx.x;
        if (gid < NT)
            g_inv[gid] = (float)(0.05 / (1.0 - pow(0.95, (double)(gid + 1))));
    }
}

// ---- fused scan ----
__global__ void __launch_bounds__(NTHREADS)
scan_kernel(const int* __restrict__ idx, float* __restrict__ out)
{
    const int dg    = blockIdx.x;
    const int chunk = blockIdx.y;
    const int b     = blockIdx.z;
    const int t0    = chunk * CLEN;
    const int tid   = threadIdx.x;

    __shared__ uint32_t s_bits[RWORDS + 4];
    __shared__ int      s_idx[SIDXN + 2];                // row byte offsets
    __shared__ unsigned long long s_inv2[CLEN];          // packed {inv, inv}
    __shared__ unsigned long long s_lut[16];             // packed {c_j, c_j+1}

    // c LUT: index [f1 f0 y1 y0]; c = 0.3*(f?-1:+1) + 0.7*(y?-1:+1)
    if (tid < 16) {
        float c0 = ((tid & 4) ? -0.3f : 0.3f) + ((tid & 1) ? -0.7f : 0.7f);
        float c1 = ((tid & 8) ? -0.3f : 0.3f) + ((tid & 2) ? -0.7f : 0.7f);
        s_lut[tid] = pk2(__float_as_uint(c0), __float_as_uint(c1));
    }
    // stage packed codebook slice (contiguous uint4 copy, L2-resident source)
    {
        const uint4* src = (const uint4*)(g_bitsx + dg * RWORDS);
        uint4*       dst = (uint4*)s_bits;
        for (int k = tid; k < RWORDS / 4; k += NTHREADS) dst[k] = src[k];
    }
    const int nwarm = chunk ? WUP : 0;
    const int ts    = t0 - nwarm;          // first scanned timestep
    for (int k = tid; k < SIDXN; k += NTHREADS) {
        int t = ts - 2 + k;                // tail entries past nsteps are unused
        s_idx[k] = ((t >= 0 && t < NT) ? idx[b * NT + t] : 0) * ROWB;
    }
    if (chunk < 2) {                       // chunks >= 2: t >= 512 -> inv = 0.05f
        for (int k = tid; k < CLEN; k += NTHREADS) {
            float v = g_inv[t0 + k];
            s_inv2[k] = pk2(__float_as_uint(v), __float_as_uint(v));
        }
    }
    __syncthreads();

    // bit field: global dim (dg*512 + m) lives at staged-row bit (32 + m);
    // this thread needs dims d-2 .. d+3 => bits starting at p = 30 + 4*tid.
    // Both f (cur) and Y (trigram) carry dim j's sign at bit (2+j).
    const int p   = 30 + 4 * tid;
    const int q   = p >> 5;
    const int rsh = p & 31;
    const char* bbase = (const char*)(s_bits + q);
    const char* lutb  = (const char*)s_lut;

    uint32_t h1s = 0, h2s = 0;   // histories pre-shifted: f_{t-1}<<1, f_{t-2}<<2
    if (ts >= 2) {               // real history (chunk >= 1)
        const uint32_t* w1 = (const uint32_t*)(bbase + s_idx[1]);
        const uint32_t* w2 = (const uint32_t*)(bbase + s_idx[0]);
        h1s = __funnelshift_r(w1[0], w1[1], rsh) << 1;
        h2s = __funnelshift_r(w2[0], w2[1], rsh) << 2;
    }

    unsigned long long a01 = 0ull, a23 = 0ull;   // packed fp32 accumulators
    float* op = out + ((size_t)b * NT + t0) * DDIM + dg * 512 + 4 * tid;

    // one LUT step body (f given), updates accs only
#define LSTEP(F, H1, H2)                                                      \
        const uint32_t Y_ = (F) ^ (H1) ^ (H2);                                \
        const uint32_t o01_ = (((F) & 12u) | ((Y_ >> 2) & 3u)) << 3;          \
        const uint32_t o23_ = ((((F) >> 2) & 12u) | ((Y_ >> 4) & 3u)) << 3;   \
        FMA2(a01, a01, G2, *(const unsigned long long*)(lutb + o01_));        \
        FMA2(a23, a23, G2, *(const unsigned long long*)(lutb + o23_));

#define EMITV(IV)                                                             \
        unsigned long long o01v, o23v;                                        \
        MUL2(o01v, a01, (IV));                                                \
        MUL2(o23v, a23, (IV));                                                \
        asm volatile("st.global.v2.b64 [%0], {%1, %2};"                       \
                     :: "l"(op), "l"(o01v), "l"(o23v) : "memory");            \
        op += DDIM;

    // paired core: sp even; E0/E1 run after each step's acc update
#define CORE2(sp, E0, E1)                                                     \
    {                                                                         \
        const int2 ofs = *(const int2*)(s_idx + (sp));                        \
        const uint32_t* wpA = (const uint32_t*)(bbase + ofs.x);               \
        const uint32_t fA = __funnelshift_r(wpA[0], wpA[1], rsh);             \
        const uint32_t* wpB = (const uint32_t*)(bbase + ofs.y);               \
        const uint32_t fB = __funnelshift_r(wpB[0], wpB[1], rsh);             \
        { LSTEP(fA, h1s, h2s) }                                               \
        E0                                                                    \
        { LSTEP(fB, fA << 1, h1s << 1) }                                      \
        E1                                                                    \
        h2s = fA << 2;                                                        \
        h1s = fB << 1;                                                        \
    }

    // u-only single step for t = 0,1 (reference zeroes shifted-history rows)
#define CORE0(sp)                                                             \
    {                                                                         \
        const uint32_t* wp = (const uint32_t*)(bbase + s_idx[(sp)]);          \
        const uint32_t f = __funnelshift_r(wp[0], wp[1], rsh);                \
        const uint32_t u0 = ((f << 29) & 0x80000000u) | 0x3E99999Au;          \
        const uint32_t u1 = ((f << 28) & 0x80000000u) | 0x3E99999Au;          \
        const uint32_t u2 = ((f << 27) & 0x80000000u) | 0x3E99999Au;          \
        const uint32_t u3 = ((f << 26) & 0x80000000u) | 0x3E99999Au;          \
        FMA2(a01, a01, G2, pk2(u0, u1));                                      \
        FMA2(a23, a23, G2, pk2(u2, u3));                                      \
        h2s = h1s << 1;                                                       \
        h1s = f << 1;                                                         \
    }

    if (chunk == 0) {
        { CORE0(2) EMITV(s_inv2[0]) }
        { CORE0(3) EMITV(s_inv2[1]) }
#pragma unroll 8
        for (int s = 2; s < CLEN; s += 2) {
            const unsigned long long* ivp = &s_inv2[s];
            CORE2(s + 2, { EMITV(ivp[0]) }, { EMITV(ivp[1]) })
        }
    } else {
        // ---- warmup: 128 store-free steps (ts >= 128, history always real) ----
#pragma unroll 8
        for (int w = 0; w < WUP; w += 2) { CORE2(w + 2, {}, {}) }
        // ---- store phase ----
        if (chunk < 2) {                 // chunk 1: t in [256,512) needs table
#pragma unroll 8
            for (int s = 0; s < CLEN; s += 2) {
                const unsigned long long* ivp = &s_inv2[s];
                CORE2(WUP + s + 2, { EMITV(ivp[0]) }, { EMITV(ivp[1]) })
            }
        } else {       // t >= 512: (1-g)/(1-g^(t+1)) == 0.05f exactly in fp32
#pragma unroll 8
            for (int s = 0; s < CLEN; s += 2) {
                CORE2(WUP + s + 2, { EMITV(INV05) }, { EMITV(INV05) })
            }
        }
    }
#undef LSTEP
#undef EMITV
#undef CORE2
#undef CORE0
}

extern "C" void kernel_launch(void* const* d_in, const int* in_sizes, int n_in,
                              void* d_out, int out_size)
{
    const float* cb  = (const float*)d_in[0];   // (256, 4096) f32 bipolar
    const int*   idx = (const int*)d_in[1];     // (8, 2048) i32
    float*       out = (float*)d_out;           // (8, 2048, 4096) f32

    dim3 pgrid(256, 4);
    pack_kernel<<<pgrid, NTHREADS>>>(cb);

    dim3 grid(NDG, NCHUNK, NB);                 // 8 x 8 x 8 = 512 blocks
    scan_kernel<<<grid, NTHREADS>>>(idx, out);
}